// round 2
// baseline (speedup 1.0000x reference)
#include <cuda_runtime.h>
#include <math.h>
#include <stdint.h>

#define NMAX 50000
#define EMAX 1600000
#define DIM  128
#define RR   8
#define HN   8
#define DK   16

#define WT_STR 132   // padded row stride for W^T tile (bank-conflict-free, 16B aligned)
#define XS_STR 68    // padded row stride for X^T tile

// ---------------- scratch (device globals; no allocations) ----------------
__device__ float g_k   [(size_t)NMAX * DIM];
__device__ float g_q   [(size_t)NMAX * DIM];
__device__ float g_v   [(size_t)NMAX * DIM];
__device__ float g_krel[(size_t)RR * NMAX * DIM];
__device__ float g_vrel[(size_t)RR * NMAX * DIM];
__device__ float g_ex  [(size_t)EMAX * HN];
__device__ float g_den [(size_t)NMAX * RR * HN];
__device__ float g_nri [(size_t)NMAX];
__device__ float g_t   [(size_t)NMAX * DIM];

// ---------------- zero ----------------
__global__ void zero_buf(float* __restrict__ p, size_t cnt) {
    size_t i = (size_t)blockIdx.x * blockDim.x + threadIdx.x;
    if (i < cnt) p[i] = 0.0f;
}

// ---------------- GEMM: Y[N,128] = X[N,128] @ W^T + b (MODE1: final epilogue) --------
// block = 256 threads, 64-node tile, full K=128 resident in smem.
template<int MODE>
__global__ __launch_bounds__(256, 2)
void gemm128(const float* __restrict__ X, const float* __restrict__ W,
             const float* __restrict__ bias, float* __restrict__ Y,
             const float* __restrict__ dsth, const float* __restrict__ skipv,
             const float* __restrict__ nri, int n)
{
    extern __shared__ float sm[];
    float* wt = sm;                     // wt[k][o], stride WT_STR
    float* xs = sm + DIM * WT_STR;      // xs[k][node], stride XS_STR

    const int tid   = threadIdx.x;
    const int tile0 = blockIdx.x * 64;

    // W^T into smem (coalesced float4 loads, transposed stores)
    const float4* W4 = (const float4*)W;
    #pragma unroll 4
    for (int i = tid; i < DIM * DIM / 4; i += 256) {
        int o  = i >> 5;
        int k4 = (i & 31) << 2;
        float4 w = W4[i];
        wt[(k4 + 0) * WT_STR + o] = w.x;
        wt[(k4 + 1) * WT_STR + o] = w.y;
        wt[(k4 + 2) * WT_STR + o] = w.z;
        wt[(k4 + 3) * WT_STR + o] = w.w;
    }
    // X tile transposed into smem
    #pragma unroll 2
    for (int i = tid; i < 64 * DIM / 4; i += 256) {
        int node = i >> 5;
        int k4   = (i & 31) << 2;
        int gn   = tile0 + node;
        float4 x = make_float4(0.f, 0.f, 0.f, 0.f);
        float  sc = 1.0f;
        if (gn < n) {
            x = *(const float4*)(X + (size_t)gn * DIM + k4);
            if (MODE == 1) sc = nri[gn];
        }
        xs[(k4 + 0) * XS_STR + node] = x.x * sc;
        xs[(k4 + 1) * XS_STR + node] = x.y * sc;
        xs[(k4 + 2) * XS_STR + node] = x.z * sc;
        xs[(k4 + 3) * XS_STR + node] = x.w * sc;
    }
    __syncthreads();

    const int to = tid & 31;   // output quad: o = to*4 .. to*4+3
    const int tn = tid >> 5;   // node group: nodes tn*8 .. tn*8+7

    float acc[8][4];
    #pragma unroll
    for (int j = 0; j < 8; j++)
        #pragma unroll
        for (int c = 0; c < 4; c++) acc[j][c] = 0.f;

    const float* wp = wt + to * 4;
    const float* xp = xs + tn * 8;

    #pragma unroll 4
    for (int kk = 0; kk < DIM; kk++) {
        float4 w  = *(const float4*)(wp + (size_t)kk * WT_STR);
        float4 xa = *(const float4*)(xp + (size_t)kk * XS_STR);
        float4 xb = *(const float4*)(xp + (size_t)kk * XS_STR + 4);
        float xv[8] = {xa.x, xa.y, xa.z, xa.w, xb.x, xb.y, xb.z, xb.w};
        float wv[4] = {w.x, w.y, w.z, w.w};
        #pragma unroll
        for (int j = 0; j < 8; j++)
            #pragma unroll
            for (int c = 0; c < 4; c++)
                acc[j][c] = fmaf(xv[j], wv[c], acc[j][c]);
    }

    float4 b4 = *(const float4*)(bias + to * 4);
    float alpha = 1.f, beta = 0.f;
    if (MODE == 1) {
        float s = skipv[0];
        alpha = 1.0f / (1.0f + __expf(-s));
        beta  = 1.0f - alpha;
    }

    #pragma unroll
    for (int j = 0; j < 8; j++) {
        int gn = tile0 + tn * 8 + j;
        if (gn >= n) continue;
        float4 r;
        r.x = acc[j][0] + b4.x;
        r.y = acc[j][1] + b4.y;
        r.z = acc[j][2] + b4.z;
        r.w = acc[j][3] + b4.w;
        if (MODE == 1) {
            float4 dh = *(const float4*)(dsth + (size_t)gn * DIM + to * 4);
            r.x = alpha * r.x + beta * dh.x;
            r.y = alpha * r.y + beta * dh.y;
            r.z = alpha * r.z + beta * dh.z;
            r.w = alpha * r.w + beta * dh.w;
        }
        *(float4*)(Y + (size_t)gn * DIM + to * 4) = r;
    }
}

// ---------------- relation transforms: k_rel/v_rel[r,n,h,:] = x[n,h,:] @ A[r,h] ------
__global__ __launch_bounds__(256, 2)
void reltrans(const float* __restrict__ K, const float* __restrict__ V,
              const float* __restrict__ Aatt, const float* __restrict__ Amsg,
              float* __restrict__ KR, float* __restrict__ VR, int n)
{
    extern __shared__ float sm[];
    float* ks = sm;                    // [128][XS_STR]
    float* vs = sm + DIM * XS_STR;

    const int tid   = threadIdx.x;
    const int tile0 = blockIdx.x * 64;

    #pragma unroll 2
    for (int i = tid; i < 64 * DIM / 4; i += 256) {
        int node = i >> 5;
        int k4   = (i & 31) << 2;
        int gn   = tile0 + node;
        float4 a = make_float4(0.f, 0.f, 0.f, 0.f);
        float4 b = make_float4(0.f, 0.f, 0.f, 0.f);
        if (gn < n) {
            a = *(const float4*)(K + (size_t)gn * DIM + k4);
            b = *(const float4*)(V + (size_t)gn * DIM + k4);
        }
        ks[(k4 + 0) * XS_STR + node] = a.x;
        ks[(k4 + 1) * XS_STR + node] = a.y;
        ks[(k4 + 2) * XS_STR + node] = a.z;
        ks[(k4 + 3) * XS_STR + node] = a.w;
        vs[(k4 + 0) * XS_STR + node] = b.x;
        vs[(k4 + 1) * XS_STR + node] = b.y;
        vs[(k4 + 2) * XS_STR + node] = b.z;
        vs[(k4 + 3) * XS_STR + node] = b.w;
    }
    __syncthreads();

    const int to = tid & 31;
    const int tn = tid >> 5;
    const int h  = to >> 2;            // head of this output quad
    const int e0 = (to & 3) << 2;      // e' start within head

    for (int r = 0; r < RR; r++) {
        // ---- K tensor ----
        {
            float acc[8][4];
            #pragma unroll
            for (int j = 0; j < 8; j++)
                #pragma unroll
                for (int c = 0; c < 4; c++) acc[j][c] = 0.f;
            #pragma unroll
            for (int d = 0; d < DK; d++) {
                float4 a = __ldg((const float4*)(Aatt + ((((size_t)r * HN + h) * DK + d) * DK + e0)));
                int dim = h * DK + d;
                float4 xa = *(const float4*)(ks + (size_t)dim * XS_STR + tn * 8);
                float4 xb = *(const float4*)(ks + (size_t)dim * XS_STR + tn * 8 + 4);
                float xv[8] = {xa.x, xa.y, xa.z, xa.w, xb.x, xb.y, xb.z, xb.w};
                float av[4] = {a.x, a.y, a.z, a.w};
                #pragma unroll
                for (int j = 0; j < 8; j++)
                    #pragma unroll
                    for (int c = 0; c < 4; c++)
                        acc[j][c] = fmaf(xv[j], av[c], acc[j][c]);
            }
            #pragma unroll
            for (int j = 0; j < 8; j++) {
                int gn = tile0 + tn * 8 + j;
                if (gn >= n) continue;
                float4 rr = make_float4(acc[j][0], acc[j][1], acc[j][2], acc[j][3]);
                *(float4*)(KR + ((size_t)r * NMAX + gn) * DIM + to * 4) = rr;
            }
        }
        // ---- V tensor ----
        {
            float acc[8][4];
            #pragma unroll
            for (int j = 0; j < 8; j++)
                #pragma unroll
                for (int c = 0; c < 4; c++) acc[j][c] = 0.f;
            #pragma unroll
            for (int d = 0; d < DK; d++) {
                float4 a = __ldg((const float4*)(Amsg + ((((size_t)r * HN + h) * DK + d) * DK + e0)));
                int dim = h * DK + d;
                float4 xa = *(const float4*)(vs + (size_t)dim * XS_STR + tn * 8);
                float4 xb = *(const float4*)(vs + (size_t)dim * XS_STR + tn * 8 + 4);
                float xv[8] = {xa.x, xa.y, xa.z, xa.w, xb.x, xb.y, xb.z, xb.w};
                float av[4] = {a.x, a.y, a.z, a.w};
                #pragma unroll
                for (int j = 0; j < 8; j++)
                    #pragma unroll
                    for (int c = 0; c < 4; c++)
                        acc[j][c] = fmaf(xv[j], av[c], acc[j][c]);
            }
            #pragma unroll
            for (int j = 0; j < 8; j++) {
                int gn = tile0 + tn * 8 + j;
                if (gn >= n) continue;
                float4 rr = make_float4(acc[j][0], acc[j][1], acc[j][2], acc[j][3]);
                *(float4*)(VR + ((size_t)r * NMAX + gn) * DIM + to * 4) = rr;
            }
        }
    }
}

// ---------------- edge pass 1: attention logits -> ex, den ----------------
// one warp per edge; lane l covers floats [4l,4l+4) of the 128-d vectors.
__global__ __launch_bounds__(256)
void edge_att(const int* __restrict__ src, const int* __restrict__ dst,
              const int* __restrict__ et, const float* __restrict__ pri,
              const float* __restrict__ Q, const float* __restrict__ KR,
              float* __restrict__ EX, float* __restrict__ DEN, int e)
{
    int gw   = (int)(((size_t)blockIdx.x * blockDim.x + threadIdx.x) >> 5);
    int lane = threadIdx.x & 31;
    if (gw >= e) return;
    int s = src[gw], d = dst[gw], r = et[gw];
    float4 kk = *(const float4*)(KR + ((size_t)r * NMAX + s) * DIM + lane * 4);
    float4 qq = *(const float4*)(Q + (size_t)d * DIM + lane * 4);
    float p = kk.x * qq.x + kk.y * qq.y + kk.z * qq.z + kk.w * qq.w;
    p += __shfl_xor_sync(0xffffffffu, p, 1);
    p += __shfl_xor_sync(0xffffffffu, p, 2);
    if ((lane & 3) == 0) {
        int h = lane >> 2;
        float att = p * pri[r * HN + h] * 0.25f;   // /sqrt(DK) = /4
        float ex = __expf(att);                     // softmax shift cancels exactly
        EX[(size_t)gw * HN + h] = ex;
        atomicAdd(DEN + ((size_t)d * RR + r) * HN + h, ex);
    }
}

// ---------------- relation presence count ----------------
__global__ void nrel_kernel(const float* __restrict__ DEN, float* __restrict__ NRI, int n)
{
    int i = blockIdx.x * blockDim.x + threadIdx.x;
    if (i >= n) return;
    int c = 0;
    #pragma unroll
    for (int r = 0; r < RR; r++)
        c += (DEN[((size_t)i * RR + r) * HN] > 0.f) ? 1 : 0;
    NRI[i] = 1.0f / (float)(c > 0 ? c : 1);
}

// ---------------- edge pass 2: weighted message aggregation ----------------
__global__ __launch_bounds__(256)
void edge_msg(const int* __restrict__ src, const int* __restrict__ dst,
              const int* __restrict__ et, const float* __restrict__ VR,
              const float* __restrict__ EX, const float* __restrict__ DEN,
              float* __restrict__ T, int e)
{
    int gw   = (int)(((size_t)blockIdx.x * blockDim.x + threadIdx.x) >> 5);
    int lane = threadIdx.x & 31;
    if (gw >= e) return;
    int s = src[gw], d = dst[gw], r = et[gw];
    float4 vv = *(const float4*)(VR + ((size_t)r * NMAX + s) * DIM + lane * 4);
    int h = lane >> 2;
    float ex  = EX[(size_t)gw * HN + h];
    float den = DEN[((size_t)d * RR + r) * HN + h];
    float a = ex / den;
    float cx = a * vv.x, cy = a * vv.y, cz = a * vv.z, cw = a * vv.w;
    float* tp = T + (size_t)d * DIM + lane * 4;
    asm volatile("red.global.add.v4.f32 [%0], {%1,%2,%3,%4};"
                 :: "l"(tp), "f"(cx), "f"(cy), "f"(cz), "f"(cw) : "memory");
}

// ---------------- launcher ----------------
extern "C" void kernel_launch(void* const* d_in, const int* in_sizes, int n_in,
                              void* d_out, int out_size)
{
    const float* src_h  = (const float*)d_in[0];
    const float* dst_h  = (const float*)d_in[1];
    const float* Wk     = (const float*)d_in[2];
    const float* bk     = (const float*)d_in[3];
    const float* Wq     = (const float*)d_in[4];
    const float* bq     = (const float*)d_in[5];
    const float* Wv     = (const float*)d_in[6];
    const float* bv     = (const float*)d_in[7];
    const float* Wa     = (const float*)d_in[8];
    const float* ba     = (const float*)d_in[9];
    const float* relpri = (const float*)d_in[10];
    const float* relatt = (const float*)d_in[11];
    const float* relmsg = (const float*)d_in[12];
    const float* skip   = (const float*)d_in[13];
    const int*   sidx   = (const int*)d_in[14];
    const int*   didx   = (const int*)d_in[15];
    const int*   etype  = (const int*)d_in[16];

    int n = in_sizes[0] / DIM;
    int e = in_sizes[14];
    if (n > NMAX) n = NMAX;
    if (e > EMAX) e = EMAX;

    float *pk, *pq, *pv, *pkr, *pvr, *pex, *pden, *pnri, *pt;
    cudaGetSymbolAddress((void**)&pk,   g_k);
    cudaGetSymbolAddress((void**)&pq,   g_q);
    cudaGetSymbolAddress((void**)&pv,   g_v);
    cudaGetSymbolAddress((void**)&pkr,  g_krel);
    cudaGetSymbolAddress((void**)&pvr,  g_vrel);
    cudaGetSymbolAddress((void**)&pex,  g_ex);
    cudaGetSymbolAddress((void**)&pden, g_den);
    cudaGetSymbolAddress((void**)&pnri, g_nri);
    cudaGetSymbolAddress((void**)&pt,   g_t);

    const int SMEM_GEMM = (DIM * WT_STR + DIM * XS_STR) * 4;   // 102400 B
    const int SMEM_RT   = 2 * DIM * XS_STR * 4;                // 69632 B
    cudaFuncSetAttribute(gemm128<0>, cudaFuncAttributeMaxDynamicSharedMemorySize, SMEM_GEMM);
    cudaFuncSetAttribute(gemm128<1>, cudaFuncAttributeMaxDynamicSharedMemorySize, SMEM_GEMM);
    cudaFuncSetAttribute(reltrans,   cudaFuncAttributeMaxDynamicSharedMemorySize, SMEM_RT);

    // zero den + t
    {
        size_t cden = (size_t)n * RR * HN;
        size_t ct   = (size_t)n * DIM;
        zero_buf<<<(unsigned)((cden + 255) / 256), 256>>>(pden, cden);
        zero_buf<<<(unsigned)((ct + 255) / 256), 256>>>(pt, ct);
    }

    unsigned tiles = (unsigned)((n + 63) / 64);
    gemm128<0><<<tiles, 256, SMEM_GEMM>>>(src_h, Wk, bk, pk, nullptr, nullptr, nullptr, n);
    gemm128<0><<<tiles, 256, SMEM_GEMM>>>(src_h, Wv, bv, pv, nullptr, nullptr, nullptr, n);
    gemm128<0><<<tiles, 256, SMEM_GEMM>>>(dst_h, Wq, bq, pq, nullptr, nullptr, nullptr, n);

    reltrans<<<tiles, 256, SMEM_RT>>>(pk, pv, relatt, relmsg, pkr, pvr, n);

    unsigned eb = (unsigned)((e + 7) / 8);   // 8 warps (edges) per 256-thread block
    edge_att<<<eb, 256>>>(sidx, didx, etype, relpri, pq, pkr, pex, pden, e);
    nrel_kernel<<<(unsigned)((n + 255) / 256), 256>>>(pden, pnri, n);
    edge_msg<<<eb, 256>>>(sidx, didx, etype, pvr, pex, pden, pt, e);

    gemm128<1><<<tiles, 256, SMEM_GEMM>>>(pt, Wa, ba, (float*)d_out, dst_h, skip, pnri, n);
}

// round 3
// speedup vs baseline: 1.1777x; 1.1777x over previous
#include <cuda_runtime.h>
#include <math.h>
#include <stdint.h>

#define NMAX 50000
#define EMAX 1600000
#define DIM  128
#define RR   8
#define HN   8
#define DK   16

#define AS_STR 132   // gemm smem stride (mod32=4 -> conflict-free with paired-k fill)
#define XS_STR 68    // reltrans smem stride (mod32=4)

typedef unsigned long long ull;

__device__ __forceinline__ ull pack2(float a, float b) {
    ull r; asm("mov.b64 %0, {%1,%2};" : "=l"(r) : "f"(a), "f"(b)); return r;
}
__device__ __forceinline__ float2 unpack2(ull a) {
    float2 v; asm("mov.b64 {%0,%1}, %2;" : "=f"(v.x), "=f"(v.y) : "l"(a)); return v;
}
__device__ __forceinline__ ull fma2(ull a, ull b, ull c) {
    ull d; asm("fma.rn.f32x2 %0, %1, %2, %3;" : "=l"(d) : "l"(a), "l"(b), "l"(c)); return d;
}

// ---------------- scratch ----------------
__device__ float g_k   [(size_t)NMAX * DIM];
__device__ float g_q   [(size_t)NMAX * DIM];
__device__ float g_v   [(size_t)NMAX * DIM];
__device__ float g_krel[(size_t)RR * NMAX * DIM];
__device__ float g_vrel[(size_t)RR * NMAX * DIM];
__device__ float g_ex  [(size_t)EMAX * HN];
__device__ float g_den [(size_t)NMAX * RR * HN];
__device__ float g_nri [(size_t)NMAX];
__device__ float g_t   [(size_t)NMAX * DIM];
__device__ int   g_ssrc[EMAX];
__device__ int   g_sdst[EMAX];
__device__ int   g_srel[EMAX];
__device__ int   g_cnt [RR];
__device__ int   g_cur [RR];

// ---------------- zero helpers ----------------
__global__ void zero_buf(float* __restrict__ p, size_t cnt) {
    size_t i = (size_t)blockIdx.x * blockDim.x + threadIdx.x;
    if (i < cnt) p[i] = 0.0f;
}
__global__ void zero_cnt() {
    int i = threadIdx.x;
    if (i < RR) { g_cnt[i] = 0; g_cur[i] = 0; }
}

// ---------------- relation sort (counting sort, 8 bins) ----------------
__global__ void hist_kernel(const int* __restrict__ et, int e) {
    __shared__ int h[RR];
    if (threadIdx.x < RR) h[threadIdx.x] = 0;
    __syncthreads();
    for (int i = blockIdx.x * blockDim.x + threadIdx.x; i < e; i += gridDim.x * blockDim.x)
        atomicAdd(&h[et[i]], 1);
    __syncthreads();
    if (threadIdx.x < RR) atomicAdd(&g_cnt[threadIdx.x], h[threadIdx.x]);
}
__global__ void offs_kernel() {
    if (threadIdx.x == 0) {
        int s = 0;
        for (int r = 0; r < RR; r++) { g_cur[r] = s; s += g_cnt[r]; }
    }
}
__global__ void scatter_kernel(const int* __restrict__ src, const int* __restrict__ dst,
                               const int* __restrict__ et, int e) {
    __shared__ int loc[RR], base[RR];
    if (threadIdx.x < RR) loc[threadIdx.x] = 0;
    __syncthreads();
    int i = blockIdx.x * blockDim.x + threadIdx.x;
    int r = -1, rank = 0, s = 0, d = 0;
    if (i < e) {
        r = et[i]; s = src[i]; d = dst[i];
        rank = atomicAdd(&loc[r], 1);
    }
    __syncthreads();
    if (threadIdx.x < RR) base[threadIdx.x] = atomicAdd(&g_cur[threadIdx.x], loc[threadIdx.x]);
    __syncthreads();
    if (i < e) {
        int pos = base[r] + rank;
        g_ssrc[pos] = s; g_sdst[pos] = d; g_srel[pos] = r;
    }
}

// ---------------- GEMM v2: Y[N,128] = X@W^T + b ; 128-node tile, f32x2 FMA --------
// 256 threads = 16x16; thread micro-tile = 8 nodes x 8 outs (node-pairs packed).
template<int MODE>
__global__ __launch_bounds__(256, 2)
void gemm_v2(const float* __restrict__ X, const float* __restrict__ W,
             const float* __restrict__ bias, float* __restrict__ Y,
             const float* __restrict__ dsth, const float* __restrict__ skipv,
             const float* __restrict__ nri, int n)
{
    __shared__ __align__(16) float As[8 * AS_STR];
    __shared__ __align__(16) float Bs[8 * AS_STR];

    const int tid = threadIdx.x;
    const int tx = tid & 15;
    const int ty = tid >> 4;
    const int tile0 = blockIdx.x * 128;

    ull acc[4][8];
    #pragma unroll
    for (int j = 0; j < 4; j++)
        #pragma unroll
        for (int o = 0; o < 8; o++) acc[j][o] = 0ull;

    const int lnode = tid >> 1;          // 0..127 (node for A, output-row for B)
    const int lk4   = (tid & 1) << 2;    // 0 or 4
    const int gnode = tile0 + lnode;
    const bool nok  = gnode < n;
    float nsc = 1.0f;
    if (MODE == 1 && nok) nsc = nri[gnode];
    const float* xp = X + (size_t)gnode * DIM + lk4;
    const float* wp = W + (size_t)lnode * DIM + lk4;

    for (int k0 = 0; k0 < DIM; k0 += 8) {
        float4 xa = make_float4(0.f, 0.f, 0.f, 0.f);
        if (nok) {
            xa = *(const float4*)(xp + k0);
            if (MODE == 1) { xa.x *= nsc; xa.y *= nsc; xa.z *= nsc; xa.w *= nsc; }
        }
        float4 wa = *(const float4*)(wp + k0);
        __syncthreads();
        // conflict-free transposed stores: bank = 16*(tid&1) + 4c + lnode/... all 32 distinct
        As[(lk4 + 0) * AS_STR + lnode] = xa.x;
        As[(lk4 + 1) * AS_STR + lnode] = xa.y;
        As[(lk4 + 2) * AS_STR + lnode] = xa.z;
        As[(lk4 + 3) * AS_STR + lnode] = xa.w;
        Bs[(lk4 + 0) * AS_STR + lnode] = wa.x;
        Bs[(lk4 + 1) * AS_STR + lnode] = wa.y;
        Bs[(lk4 + 2) * AS_STR + lnode] = wa.z;
        Bs[(lk4 + 3) * AS_STR + lnode] = wa.w;
        __syncthreads();
        #pragma unroll
        for (int kk = 0; kk < 8; kk++) {
            ulonglong2 a01 = *(const ulonglong2*)(As + kk * AS_STR + ty * 8);
            ulonglong2 a23 = *(const ulonglong2*)(As + kk * AS_STR + ty * 8 + 4);
            float4 b0 = *(const float4*)(Bs + kk * AS_STR + tx * 8);
            float4 b1 = *(const float4*)(Bs + kk * AS_STR + tx * 8 + 4);
            ull av[4] = {a01.x, a01.y, a23.x, a23.y};
            ull bv[8] = {pack2(b0.x, b0.x), pack2(b0.y, b0.y), pack2(b0.z, b0.z), pack2(b0.w, b0.w),
                         pack2(b1.x, b1.x), pack2(b1.y, b1.y), pack2(b1.z, b1.z), pack2(b1.w, b1.w)};
            #pragma unroll
            for (int j = 0; j < 4; j++)
                #pragma unroll
                for (int o = 0; o < 8; o++)
                    acc[j][o] = fma2(av[j], bv[o], acc[j][o]);
        }
    }

    float bb[8];
    {
        float4 c0 = *(const float4*)(bias + tx * 8);
        float4 c1 = *(const float4*)(bias + tx * 8 + 4);
        bb[0] = c0.x; bb[1] = c0.y; bb[2] = c0.z; bb[3] = c0.w;
        bb[4] = c1.x; bb[5] = c1.y; bb[6] = c1.z; bb[7] = c1.w;
    }
    float alpha = 1.f, beta = 0.f;
    if (MODE == 1) {
        float s = skipv[0];
        alpha = 1.0f / (1.0f + __expf(-s));
        beta  = 1.0f - alpha;
    }

    #pragma unroll
    for (int j = 0; j < 4; j++) {
        float2 u[8];
        #pragma unroll
        for (int o = 0; o < 8; o++) u[o] = unpack2(acc[j][o]);
        #pragma unroll
        for (int half = 0; half < 2; half++) {
            int gn = tile0 + ty * 8 + j * 2 + half;
            if (gn >= n) continue;
            float v[8];
            #pragma unroll
            for (int o = 0; o < 8; o++) v[o] = (half ? u[o].y : u[o].x) + bb[o];
            if (MODE == 1) {
                float4 d0 = *(const float4*)(dsth + (size_t)gn * DIM + tx * 8);
                float4 d1 = *(const float4*)(dsth + (size_t)gn * DIM + tx * 8 + 4);
                v[0] = alpha * v[0] + beta * d0.x; v[1] = alpha * v[1] + beta * d0.y;
                v[2] = alpha * v[2] + beta * d0.z; v[3] = alpha * v[3] + beta * d0.w;
                v[4] = alpha * v[4] + beta * d1.x; v[5] = alpha * v[5] + beta * d1.y;
                v[6] = alpha * v[6] + beta * d1.z; v[7] = alpha * v[7] + beta * d1.w;
            }
            float4 r0 = make_float4(v[0], v[1], v[2], v[3]);
            float4 r1 = make_float4(v[4], v[5], v[6], v[7]);
            *(float4*)(Y + (size_t)gn * DIM + tx * 8)     = r0;
            *(float4*)(Y + (size_t)gn * DIM + tx * 8 + 4) = r1;
        }
    }
}

// ---------------- relation transforms (f32x2, conflict-free fill) ----------------
__global__ __launch_bounds__(256, 2)
void reltrans(const float* __restrict__ K, const float* __restrict__ V,
              const float* __restrict__ Aatt, const float* __restrict__ Amsg,
              float* __restrict__ KR, float* __restrict__ VR, int n)
{
    extern __shared__ __align__(16) float sm[];
    float* ks = sm;                    // [128 dim][XS_STR nodes]
    float* vs = sm + DIM * XS_STR;

    const int tid   = threadIdx.x;
    const int tile0 = blockIdx.x * 64;

    #pragma unroll
    for (int it = 0; it < 8; it++) {
        int idx  = tid + it * 256;
        int node = (idx >> 1) & 63;
        int k4   = ((idx >> 7) << 3) + ((idx & 1) << 2);
        int gn   = tile0 + node;
        float4 a = make_float4(0.f, 0.f, 0.f, 0.f);
        float4 b = make_float4(0.f, 0.f, 0.f, 0.f);
        if (gn < n) {
            a = *(const float4*)(K + (size_t)gn * DIM + k4);
            b = *(const float4*)(V + (size_t)gn * DIM + k4);
        }
        ks[(k4 + 0) * XS_STR + node] = a.x; ks[(k4 + 1) * XS_STR + node] = a.y;
        ks[(k4 + 2) * XS_STR + node] = a.z; ks[(k4 + 3) * XS_STR + node] = a.w;
        vs[(k4 + 0) * XS_STR + node] = b.x; vs[(k4 + 1) * XS_STR + node] = b.y;
        vs[(k4 + 2) * XS_STR + node] = b.z; vs[(k4 + 3) * XS_STR + node] = b.w;
    }
    __syncthreads();

    const int to = tid & 31;
    const int tn = tid >> 5;
    const int h  = to >> 2;
    const int e0 = (to & 3) << 2;

    for (int r = 0; r < RR; r++) {
        // K tensor
        {
            ull acc[4][4];
            #pragma unroll
            for (int j = 0; j < 4; j++)
                #pragma unroll
                for (int c = 0; c < 4; c++) acc[j][c] = 0ull;
            #pragma unroll
            for (int d = 0; d < DK; d++) {
                float4 a = __ldg((const float4*)(Aatt + ((((size_t)r * HN + h) * DK + d) * DK + e0)));
                int dim = h * DK + d;
                ulonglong2 x01 = *(const ulonglong2*)(ks + (size_t)dim * XS_STR + tn * 8);
                ulonglong2 x23 = *(const ulonglong2*)(ks + (size_t)dim * XS_STR + tn * 8 + 4);
                ull xv[4] = {x01.x, x01.y, x23.x, x23.y};
                ull a2[4] = {pack2(a.x, a.x), pack2(a.y, a.y), pack2(a.z, a.z), pack2(a.w, a.w)};
                #pragma unroll
                for (int j = 0; j < 4; j++)
                    #pragma unroll
                    for (int c = 0; c < 4; c++)
                        acc[j][c] = fma2(xv[j], a2[c], acc[j][c]);
            }
            #pragma unroll
            for (int j = 0; j < 4; j++) {
                float2 u0 = unpack2(acc[j][0]), u1 = unpack2(acc[j][1]);
                float2 u2 = unpack2(acc[j][2]), u3 = unpack2(acc[j][3]);
                int gn0 = tile0 + tn * 8 + j * 2;
                if (gn0 < n) {
                    float4 rr = make_float4(u0.x, u1.x, u2.x, u3.x);
                    *(float4*)(KR + ((size_t)r * NMAX + gn0) * DIM + to * 4) = rr;
                }
                if (gn0 + 1 < n) {
                    float4 rr = make_float4(u0.y, u1.y, u2.y, u3.y);
                    *(float4*)(KR + ((size_t)r * NMAX + gn0 + 1) * DIM + to * 4) = rr;
                }
            }
        }
        // V tensor
        {
            ull acc[4][4];
            #pragma unroll
            for (int j = 0; j < 4; j++)
                #pragma unroll
                for (int c = 0; c < 4; c++) acc[j][c] = 0ull;
            #pragma unroll
            for (int d = 0; d < DK; d++) {
                float4 a = __ldg((const float4*)(Amsg + ((((size_t)r * HN + h) * DK + d) * DK + e0)));
                int dim = h * DK + d;
                ulonglong2 x01 = *(const ulonglong2*)(vs + (size_t)dim * XS_STR + tn * 8);
                ulonglong2 x23 = *(const ulonglong2*)(vs + (size_t)dim * XS_STR + tn * 8 + 4);
                ull xv[4] = {x01.x, x01.y, x23.x, x23.y};
                ull a2[4] = {pack2(a.x, a.x), pack2(a.y, a.y), pack2(a.z, a.z), pack2(a.w, a.w)};
                #pragma unroll
                for (int j = 0; j < 4; j++)
                    #pragma unroll
                    for (int c = 0; c < 4; c++)
                        acc[j][c] = fma2(xv[j], a2[c], acc[j][c]);
            }
            #pragma unroll
            for (int j = 0; j < 4; j++) {
                float2 u0 = unpack2(acc[j][0]), u1 = unpack2(acc[j][1]);
                float2 u2 = unpack2(acc[j][2]), u3 = unpack2(acc[j][3]);
                int gn0 = tile0 + tn * 8 + j * 2;
                if (gn0 < n) {
                    float4 rr = make_float4(u0.x, u1.x, u2.x, u3.x);
                    *(float4*)(VR + ((size_t)r * NMAX + gn0) * DIM + to * 4) = rr;
                }
                if (gn0 + 1 < n) {
                    float4 rr = make_float4(u0.y, u1.y, u2.y, u3.y);
                    *(float4*)(VR + ((size_t)r * NMAX + gn0 + 1) * DIM + to * 4) = rr;
                }
            }
        }
    }
}

// ---------------- edge pass 1 (relation-sorted): logits -> ex, den ----------------
__global__ __launch_bounds__(256)
void edge_att(const float* __restrict__ pri,
              const float* __restrict__ Q, const float* __restrict__ KR,
              float* __restrict__ EX, float* __restrict__ DEN, int e)
{
    int gw   = (int)(((size_t)blockIdx.x * blockDim.x + threadIdx.x) >> 5);
    int lane = threadIdx.x & 31;
    if (gw >= e) return;
    int s = g_ssrc[gw], d = g_sdst[gw], r = g_srel[gw];
    float4 kk = *(const float4*)(KR + ((size_t)r * NMAX + s) * DIM + lane * 4);
    float4 qq = *(const float4*)(Q + (size_t)d * DIM + lane * 4);
    float p = kk.x * qq.x + kk.y * qq.y + kk.z * qq.z + kk.w * qq.w;
    p += __shfl_xor_sync(0xffffffffu, p, 1);
    p += __shfl_xor_sync(0xffffffffu, p, 2);
    if ((lane & 3) == 0) {
        int h = lane >> 2;
        float att = p * pri[r * HN + h] * 0.25f;   // /sqrt(DK)=4
        float ex = __expf(att);                     // softmax shift cancels exactly
        EX[(size_t)gw * HN + h] = ex;
        atomicAdd(DEN + ((size_t)d * RR + r) * HN + h, ex);
    }
}

// ---------------- relation presence count ----------------
__global__ void nrel_kernel(const float* __restrict__ DEN, float* __restrict__ NRI, int n)
{
    int i = blockIdx.x * blockDim.x + threadIdx.x;
    if (i >= n) return;
    int c = 0;
    #pragma unroll
    for (int r = 0; r < RR; r++)
        c += (DEN[((size_t)i * RR + r) * HN] > 0.f) ? 1 : 0;
    NRI[i] = 1.0f / (float)(c > 0 ? c : 1);
}

// ---------------- edge pass 2 (relation-sorted): weighted aggregation ----------------
__global__ __launch_bounds__(256)
void edge_msg(const float* __restrict__ VR,
              const float* __restrict__ EX, const float* __restrict__ DEN,
              float* __restrict__ T, int e)
{
    int gw   = (int)(((size_t)blockIdx.x * blockDim.x + threadIdx.x) >> 5);
    int lane = threadIdx.x & 31;
    if (gw >= e) return;
    int s = g_ssrc[gw], d = g_sdst[gw], r = g_srel[gw];
    float4 vv = *(const float4*)(VR + ((size_t)r * NMAX + s) * DIM + lane * 4);
    int h = lane >> 2;
    float ex  = EX[(size_t)gw * HN + h];
    float den = DEN[((size_t)d * RR + r) * HN + h];
    float a = ex / den;
    float cx = a * vv.x, cy = a * vv.y, cz = a * vv.z, cw = a * vv.w;
    float* tp = T + (size_t)d * DIM + lane * 4;
    asm volatile("red.global.add.v4.f32 [%0], {%1,%2,%3,%4};"
                 :: "l"(tp), "f"(cx), "f"(cy), "f"(cz), "f"(cw) : "memory");
}

// ---------------- launcher ----------------
extern "C" void kernel_launch(void* const* d_in, const int* in_sizes, int n_in,
                              void* d_out, int out_size)
{
    const float* src_h  = (const float*)d_in[0];
    const float* dst_h  = (const float*)d_in[1];
    const float* Wk     = (const float*)d_in[2];
    const float* bk     = (const float*)d_in[3];
    const float* Wq     = (const float*)d_in[4];
    const float* bq     = (const float*)d_in[5];
    const float* Wv     = (const float*)d_in[6];
    const float* bv     = (const float*)d_in[7];
    const float* Wa     = (const float*)d_in[8];
    const float* ba     = (const float*)d_in[9];
    const float* relpri = (const float*)d_in[10];
    const float* relatt = (const float*)d_in[11];
    const float* relmsg = (const float*)d_in[12];
    const float* skip   = (const float*)d_in[13];
    const int*   sidx   = (const int*)d_in[14];
    const int*   didx   = (const int*)d_in[15];
    const int*   etype  = (const int*)d_in[16];

    int n = in_sizes[0] / DIM;
    int e = in_sizes[14];
    if (n > NMAX) n = NMAX;
    if (e > EMAX) e = EMAX;

    float *pk, *pq, *pv, *pkr, *pvr, *pex, *pden, *pnri, *pt;
    cudaGetSymbolAddress((void**)&pk,   g_k);
    cudaGetSymbolAddress((void**)&pq,   g_q);
    cudaGetSymbolAddress((void**)&pv,   g_v);
    cudaGetSymbolAddress((void**)&pkr,  g_krel);
    cudaGetSymbolAddress((void**)&pvr,  g_vrel);
    cudaGetSymbolAddress((void**)&pex,  g_ex);
    cudaGetSymbolAddress((void**)&pden, g_den);
    cudaGetSymbolAddress((void**)&pnri, g_nri);
    cudaGetSymbolAddress((void**)&pt,   g_t);

    const int SMEM_RT = 2 * DIM * XS_STR * 4;   // 69632 B
    cudaFuncSetAttribute(reltrans, cudaFuncAttributeMaxDynamicSharedMemorySize, SMEM_RT);

    // zero den + t + sort counters
    {
        size_t cden = (size_t)n * RR * HN;
        size_t ct   = (size_t)n * DIM;
        zero_buf<<<(unsigned)((cden + 255) / 256), 256>>>(pden, cden);
        zero_buf<<<(unsigned)((ct + 255) / 256), 256>>>(pt, ct);
        zero_cnt<<<1, 32>>>();
    }

    // relation counting sort
    hist_kernel<<<1024, 256>>>(etype, e);
    offs_kernel<<<1, 32>>>();
    scatter_kernel<<<(unsigned)((e + 255) / 256), 256>>>(sidx, didx, etype, e);

    unsigned tiles128 = (unsigned)((n + 127) / 128);
    unsigned tiles64  = (unsigned)((n + 63) / 64);
    gemm_v2<0><<<tiles128, 256>>>(src_h, Wk, bk, pk, nullptr, nullptr, nullptr, n);
    gemm_v2<0><<<tiles128, 256>>>(src_h, Wv, bv, pv, nullptr, nullptr, nullptr, n);
    gemm_v2<0><<<tiles128, 256>>>(dst_h, Wq, bq, pq, nullptr, nullptr, nullptr, n);

    reltrans<<<tiles64, 256, SMEM_RT>>>(pk, pv, relatt, relmsg, pkr, pvr, n);

    unsigned eb = (unsigned)((e + 7) / 8);
    edge_att<<<eb, 256>>>(relpri, pq, pkr, pex, pden, e);
    nrel_kernel<<<(unsigned)((n + 255) / 256), 256>>>(pden, pnri, n);
    edge_msg<<<eb, 256>>>(pvr, pex, pden, pt, e);

    gemm_v2<1><<<tiles128, 256>>>(pt, Wa, ba, (float*)d_out, dst_h, skip, pnri, n);
}